// round 13
// baseline (speedup 1.0000x reference)
#include <cuda_runtime.h>
#include <cuda_bf16.h>

#define GS 256
#define PARAM 128
#define KC 32
#define I1 64
#define I2 32
#define PK 96
#define BB 4
#define EPS 1e-3f
#define NROWS (BB * GS)   // 1024
#define MAXY 64           // per-row nonzero capacity (mean 16, max ~40)
#define NBLK (NROWS / 8)  // 128 blocks, all resident
#define BPB  (NBLK / BB)  // 32 blocks per batch

// -------- scratch (device globals; no allocation allowed) --------
__device__ float d_C[NROWS * I1];        // per-row y-part, scale folded (cross-block)
__device__ unsigned int d_bar4[BB];      // per-batch monotonic barrier counters

// ---------------- single fused kernel ----------------
// 128 blocks x 8 warps, 8 rows/block (one batch per 32 blocks).
//   pre-barrier : stage val -> layer-1 GEMM -> store C -> fence -> ARRIVE (batch ctr)
//   overlap     : fold W2/W3, compaction, A finalize, con copy, accw zero, unit list
//   wait        : nanosleep spin until 32 batch-blocks arrived
//   post        : balanced unit queue, per-warp partial slabs, combine, var writes
__global__ void __launch_bounds__(256) fused_kernel(const float* __restrict__ mat,
                                                    const float* __restrict__ val,
                                                    const float* __restrict__ M1,
                                                    const float* __restrict__ B1,
                                                    const float* __restrict__ M2,
                                                    const float* __restrict__ B2,
                                                    const float* __restrict__ M3,
                                                    const float* __restrict__ B3,
                                                    const float* __restrict__ g1,
                                                    const float* __restrict__ b1,
                                                    const float* __restrict__ m1,
                                                    const float* __restrict__ v1,
                                                    const float* __restrict__ g2,
                                                    const float* __restrict__ b2,
                                                    const float* __restrict__ m2,
                                                    const float* __restrict__ v2,
                                                    const float* __restrict__ g3,
                                                    const float* __restrict__ b3,
                                                    const float* __restrict__ m3,
                                                    const float* __restrict__ v3,
                                                    float* __restrict__ out) {
    __shared__ float W2t[I2 * 68];         // 8.5 KB folded W2, transposed [col][j]
    __shared__ float4 W3p[I2 * 32];        // 16 KB folded W3, [j][lane]=cols 3l..3l+2
    __shared__ float b2s[I2];
    __shared__ float b3s[PK];
    __shared__ float axs[8][I1];           // 2 KB  A rows (block-local)
    __shared__ int ylist[8][MAXY];         // 2 KB
    __shared__ float yvs[8][MAXY];         // 2 KB
    __shared__ int ncnt[8];
    __shared__ float s1s[8][4][I1];        // 8 KB
    __shared__ float s2s[8][4][I2];        // 4 KB
    __shared__ float vs[8][PARAM];         // 4 KB
    __shared__ float buf[2][8][I1];        // 4 KB
    __shared__ float accw[8][8][PK];       // 24 KB  per-warp row partials
    __shared__ int units[8 * (MAXY / 4)];  // 0.5 KB (rw<<8)|i0

    int t = threadIdx.x;
    int lane = t & 31;
    int w = t >> 5;              // 0..7
    int row0 = blockIdx.x * 8;
    int row = row0 + w;
    int bat = blockIdx.x >> 5;   // batch 0..3 (rows of a batch span 32 blocks)

    // ===== pre-barrier: stage val rows =====
    for (int i = t; i < 8 * PARAM; i += 256)
        vs[i >> 7][i & 127] = val[row0 * PARAM + i];
    __syncthreads();

    // ===== pre-barrier: layer-1 GEMM (both halves of M1) =====
    {
        int j = t & 63;
        int part = (t >> 6) & 1;          // 0 = M1[:128], 1 = M1[128:]
        int half = t >> 7;                // rows half*4 .. half*4+3
        float sumA[4] = {0.f, 0.f, 0.f, 0.f};
        float sumB[4] = {0.f, 0.f, 0.f, 0.f};
        const float* Mp = M1 + part * PARAM * I1 + j;
#pragma unroll
        for (int k = 0; k < PARAM; k += 8) {
            float a0 = Mp[(k + 0) * I1], a1 = Mp[(k + 1) * I1];
            float a2 = Mp[(k + 2) * I1], a3 = Mp[(k + 3) * I1];
            float c0 = Mp[(k + 4) * I1], c1 = Mp[(k + 5) * I1];
            float c2 = Mp[(k + 6) * I1], c3 = Mp[(k + 7) * I1];
#pragma unroll
            for (int r = 0; r < 4; r++) {
                float4 va = *(const float4*)&vs[half * 4 + r][k];
                float4 vb = *(const float4*)&vs[half * 4 + r][k + 4];
                sumA[r] = fmaf(va.x, a0, fmaf(va.y, a1, fmaf(va.z, a2, fmaf(va.w, a3, sumA[r]))));
                sumB[r] = fmaf(vb.x, c0, fmaf(vb.y, c1, fmaf(vb.z, c2, fmaf(vb.w, c3, sumB[r]))));
            }
        }
#pragma unroll
        for (int r = 0; r < 4; r++) buf[part][half * 4 + r][j] = sumA[r] + sumB[r];
        __syncthreads();
        if (part == 1) {
            float sc = g1[j] * rsqrtf(v1[j] + EPS);
#pragma unroll
            for (int r = 0; r < 4; r++) {
                int rr = half * 4 + r;
                d_C[(row0 + rr) * I1 + j] = buf[1][rr][j] * sc;
            }
        }
    }

    // ===== arrive on batch counter (release C writes) =====
    __threadfence();
    __syncthreads();
    if (t == 0) atomicAdd(&d_bar4[bat], 1u);

    // ===== overlap window: block-local prep while batch peers finish =====
    for (int i = t; i < I1 * I2; i += 256) {
        int col = i & 31, j = i >> 5;
        float s = g2[col] * rsqrtf(v2[col] + EPS);
        W2t[col * 68 + j] = M2[j * I2 + col] * s;
    }
    {
        float* W3f = (float*)W3p;
        for (int i = t; i < I2 * 128; i += 256) {
            int j = i >> 7, q = i & 127, l = q >> 2, d = q & 3;
            float vvv = 0.f;
            if (d < 3) {
                int col = 3 * l + d;
                vvv = M3[j * PK + col] * (g3[col] * rsqrtf(v3[col] + EPS));
            }
            W3f[i] = vvv;
        }
    }
    if (t < I2) {
        float s = g2[t] * rsqrtf(v2[t] + EPS);
        b2s[t] = B2[t] * s + (b2[t] - m2[t] * s);
    }
    if (t >= 128 && t < 128 + PK) {
        int k = t - 128;
        float s = g3[k] * rsqrtf(v3[k] + EPS);
        b3s[k] = B3[k] * s + (b3[k] - m3[k] * s);
    }
    // A finalize
    {
        int j = t & 63;
        int part = (t >> 6) & 1;
        int half = t >> 7;
        if (part == 0) {
            float sc = g1[j] * rsqrtf(v1[j] + EPS);
            float bb = B1[j] * sc + (b1[j] - m1[j] * sc);
#pragma unroll
            for (int r = 0; r < 4; r++) {
                int rr = half * 4 + r;
                axs[rr][j] = (buf[0][rr][j] - buf[1][rr][j]) * sc + bb;
            }
        }
    }
    // per-warp mask compaction
    {
        int cnt = 0;
#pragma unroll
        for (int c = 0; c < GS / 32; c++) {
            int idx = c * 32 + lane;
            float mv = mat[row * GS + idx];
            unsigned msk = __ballot_sync(0xffffffffu, mv != 0.0f);
            if (mv != 0.0f) {
                int off = cnt + __popc(msk & ((1u << lane) - 1u));
                ylist[w][off] = idx;
                yvs[w][off] = mv;
            }
            cnt += __popc(msk);
        }
        int n4 = (cnt + 3) & ~3;
        for (int k = cnt + lane; k < n4; k += 32) { ylist[w][k] = 0; yvs[w][k] = 0.f; }
        if (lane == 0) ncnt[w] = n4;
    }
    // con copy + zero partial slabs
    out[row * PARAM + lane] = vs[w][lane];
    for (int i = t; i < 8 * 8 * PK; i += 256) ((float*)accw)[i] = 0.f;
    __syncthreads();             // ncnt/accw ready

    // ===== build balanced unit list (all threads compute offsets redundantly) =====
    int nu;
    {
        int offs[8];
        int acc = 0;
#pragma unroll
        for (int r = 0; r < 8; r++) { offs[r] = acc; acc += (ncnt[r] >> 2); }
        nu = acc;
        int nb = ncnt[w] >> 2;
        if (lane < nb) units[offs[w] + lane] = (w << 8) | (lane << 2);
    }
    __syncthreads();             // units visible

    // ===== wait for batch peers (nanosleep spin) =====
    if (t == 0) {
        unsigned seen = atomicAdd(&d_bar4[bat], 0u);
        unsigned target = ((seen - 1u) / (unsigned)BPB + 1u) * (unsigned)BPB;
        while (*(volatile unsigned*)&d_bar4[bat] < target) { __nanosleep(64); }
    }
    __syncthreads();

    // ===== phase 2: balanced unit queue (warp w takes units w, w+8, ...) =====
    float b2l = b2s[lane];
    float b30 = b3s[3 * lane], b31 = b3s[3 * lane + 1], b32 = b3s[3 * lane + 2];
    const float* Cb = d_C + bat * GS * I1;   // all 8 rows share the batch

    float cl[4], ch[4];
    int u = w, rwc = 0, i0c = 0;
    if (u < nu) {
        int unit = units[u]; rwc = unit >> 8; i0c = unit & 255;
#pragma unroll
        for (int p = 0; p < 4; p++) {
            const float* cy = Cb + ylist[rwc][i0c + p] * I1;
            cl[p] = __ldg(cy + lane);
            ch[p] = __ldg(cy + lane + 32);
        }
    }

    while (u < nu) {
        int rw = rwc, i0 = i0c;
        float axl = axs[rw][lane], axh = axs[rw][lane + 32];
#pragma unroll
        for (int p = 0; p < 4; p++) {
            s1s[w][p][lane] = fmaxf(axl + cl[p], 0.f);
            s1s[w][p][lane + 32] = fmaxf(axh + ch[p], 0.f);
        }
        __syncwarp();
        int un = u + 8;
        if (un < nu) {
            int unit = units[un]; rwc = unit >> 8; i0c = unit & 255;
#pragma unroll
            for (int p = 0; p < 4; p++) {
                const float* cy = Cb + ylist[rwc][i0c + p] * I1;
                cl[p] = __ldg(cy + lane);
                ch[p] = __ldg(cy + lane + 32);
            }
        }
        // layer 2
        float s2p0 = b2l, s2p1 = b2l, s2p2 = b2l, s2p3 = b2l;
        float r0 = 0.f, r1 = 0.f, r2 = 0.f, r3 = 0.f;
        const float4* w2v = (const float4*)&W2t[lane * 68];
        const float4* v0p = (const float4*)s1s[w][0];
        const float4* v1p = (const float4*)s1s[w][1];
        const float4* v2p = (const float4*)s1s[w][2];
        const float4* v3p = (const float4*)s1s[w][3];
#pragma unroll
        for (int q = 0; q < 16; q += 2) {
            float4 wa = w2v[q], wb = w2v[q + 1];
            float4 v0 = v0p[q], v1 = v1p[q], v2 = v2p[q], v3 = v3p[q];
            float4 u0 = v0p[q + 1], u1 = v1p[q + 1], u2 = v2p[q + 1], u3 = v3p[q + 1];
            s2p0 = fmaf(v0.x, wa.x, s2p0); s2p0 = fmaf(v0.y, wa.y, s2p0);
            s2p0 = fmaf(v0.z, wa.z, s2p0); s2p0 = fmaf(v0.w, wa.w, s2p0);
            r0 = fmaf(u0.x, wb.x, r0); r0 = fmaf(u0.y, wb.y, r0);
            r0 = fmaf(u0.z, wb.z, r0); r0 = fmaf(u0.w, wb.w, r0);
            s2p1 = fmaf(v1.x, wa.x, s2p1); s2p1 = fmaf(v1.y, wa.y, s2p1);
            s2p1 = fmaf(v1.z, wa.z, s2p1); s2p1 = fmaf(v1.w, wa.w, s2p1);
            r1 = fmaf(u1.x, wb.x, r1); r1 = fmaf(u1.y, wb.y, r1);
            r1 = fmaf(u1.z, wb.z, r1); r1 = fmaf(u1.w, wb.w, r1);
            s2p2 = fmaf(v2.x, wa.x, s2p2); s2p2 = fmaf(v2.y, wa.y, s2p2);
            s2p2 = fmaf(v2.z, wa.z, s2p2); s2p2 = fmaf(v2.w, wa.w, s2p2);
            r2 = fmaf(u2.x, wb.x, r2); r2 = fmaf(u2.y, wb.y, r2);
            r2 = fmaf(u2.z, wb.z, r2); r2 = fmaf(u2.w, wb.w, r2);
            s2p3 = fmaf(v3.x, wa.x, s2p3); s2p3 = fmaf(v3.y, wa.y, s2p3);
            s2p3 = fmaf(v3.z, wa.z, s2p3); s2p3 = fmaf(v3.w, wa.w, s2p3);
            r3 = fmaf(u3.x, wb.x, r3); r3 = fmaf(u3.y, wb.y, r3);
            r3 = fmaf(u3.z, wb.z, r3); r3 = fmaf(u3.w, wb.w, r3);
        }
        s2s[w][0][lane] = fmaxf(s2p0 + r0, 0.f);
        s2s[w][1][lane] = fmaxf(s2p1 + r1, 0.f);
        s2s[w][2][lane] = fmaxf(s2p2 + r2, 0.f);
        s2s[w][3][lane] = fmaxf(s2p3 + r3, 0.f);
        __syncwarp();
        // layer 3
        float t00 = b30, t01 = b31, t02 = b32;
        float t10 = b30, t11 = b31, t12 = b32;
        float t20 = b30, t21 = b31, t22 = b32;
        float t30 = b30, t31 = b31, t32 = b32;
        const float4* u0p = (const float4*)s2s[w][0];
        const float4* u1p = (const float4*)s2s[w][1];
        const float4* u2p = (const float4*)s2s[w][2];
        const float4* u3p = (const float4*)s2s[w][3];
#pragma unroll
        for (int jq = 0; jq < 8; jq++) {
            float4 u0 = u0p[jq], u1 = u1p[jq], u2 = u2p[jq], u3 = u3p[jq];
            float s0v[4] = {u0.x, u0.y, u0.z, u0.w};
            float s1v[4] = {u1.x, u1.y, u1.z, u1.w};
            float s2v[4] = {u2.x, u2.y, u2.z, u2.w};
            float s3v[4] = {u3.x, u3.y, u3.z, u3.w};
#pragma unroll
            for (int d = 0; d < 4; d++) {
                float4 wv = W3p[(4 * jq + d) * 32 + lane];
                t00 = fmaf(s0v[d], wv.x, t00); t01 = fmaf(s0v[d], wv.y, t01); t02 = fmaf(s0v[d], wv.z, t02);
                t10 = fmaf(s1v[d], wv.x, t10); t11 = fmaf(s1v[d], wv.y, t11); t12 = fmaf(s1v[d], wv.z, t12);
                t20 = fmaf(s2v[d], wv.x, t20); t21 = fmaf(s2v[d], wv.y, t21); t22 = fmaf(s2v[d], wv.z, t22);
                t30 = fmaf(s3v[d], wv.x, t30); t31 = fmaf(s3v[d], wv.y, t31); t32 = fmaf(s3v[d], wv.z, t32);
            }
        }
        float m0 = yvs[rw][i0], m1v = yvs[rw][i0 + 1], m2v = yvs[rw][i0 + 2], m3v = yvs[rw][i0 + 3];
        float a0 = fmaxf(t00, 0.f) * m0, a1 = fmaxf(t01, 0.f) * m0, a2 = fmaxf(t02, 0.f) * m0;
        a0 = fmaf(fmaxf(t10, 0.f), m1v, a0); a1 = fmaf(fmaxf(t11, 0.f), m1v, a1); a2 = fmaf(fmaxf(t12, 0.f), m1v, a2);
        a0 = fmaf(fmaxf(t20, 0.f), m2v, a0); a1 = fmaf(fmaxf(t21, 0.f), m2v, a1); a2 = fmaf(fmaxf(t22, 0.f), m2v, a2);
        a0 = fmaf(fmaxf(t30, 0.f), m3v, a0); a1 = fmaf(fmaxf(t31, 0.f), m3v, a1); a2 = fmaf(fmaxf(t32, 0.f), m3v, a2);
        // accumulate into this warp's private slab (race-free, serial per warp)
        accw[w][rw][3 * lane + 0] += a0;
        accw[w][rw][3 * lane + 1] += a1;
        accw[w][rw][3 * lane + 2] += a2;
        u = un;
    }

    // ===== combine: warp w reduces row w over all 8 warp slabs =====
    __syncthreads();
    {
        float a0 = 0.f, a1 = 0.f, a2 = 0.f;
#pragma unroll
        for (int ww = 0; ww < 8; ww++) {
            a0 += accw[ww][w][3 * lane + 0];
            a1 += accw[ww][w][3 * lane + 1];
            a2 += accw[ww][w][3 * lane + 2];
        }
        float* orow = out + row * PARAM;
        orow[KC + 3 * lane + 0] = fminf(fmaxf(a0 * (1.f / 16.f), -1.f), 1.f);
        orow[KC + 3 * lane + 1] = fminf(fmaxf(a1 * (1.f / 16.f), -1.f), 1.f);
        orow[KC + 3 * lane + 2] = fminf(fmaxf(a2 * (1.f / 16.f), -1.f), 1.f);
    }
}

extern "C" void kernel_launch(void* const* d_in, const int* in_sizes, int n_in,
                              void* d_out, int out_size) {
    const float* mat = (const float*)d_in[0];
    const float* val = (const float*)d_in[1];
    const float* M1  = (const float*)d_in[2];
    const float* B1  = (const float*)d_in[3];
    const float* M2  = (const float*)d_in[4];
    const float* B2  = (const float*)d_in[5];
    const float* M3  = (const float*)d_in[6];
    const float* B3  = (const float*)d_in[7];
    const float* g1  = (const float*)d_in[8];
    const float* b1  = (const float*)d_in[9];
    const float* m1  = (const float*)d_in[10];
    const float* v1  = (const float*)d_in[11];
    const float* g2  = (const float*)d_in[12];
    const float* b2  = (const float*)d_in[13];
    const float* m2  = (const float*)d_in[14];
    const float* v2  = (const float*)d_in[15];
    const float* g3  = (const float*)d_in[16];
    const float* b3  = (const float*)d_in[17];
    const float* m3  = (const float*)d_in[18];
    const float* v3  = (const float*)d_in[19];
    float* out = (float*)d_out;

    fused_kernel<<<NBLK, 256>>>(mat, val, M1, B1, M2, B2, M3, B3,
                                g1, b1, m1, v1, g2, b2, m2, v2,
                                g3, b3, m3, v3, out);
}

// round 15
// speedup vs baseline: 1.4337x; 1.4337x over previous
#include <cuda_runtime.h>
#include <cuda_bf16.h>

#define GS 256
#define PARAM 128
#define KC 32
#define I1 64
#define I2 32
#define PK 96
#define BB 4
#define EPS 1e-3f
#define NROWS (BB * GS)   // 1024
#define MAXY 64           // per-row nonzero capacity (mean 16, max ~40)
#define NBLK (NROWS / 8)  // 128 blocks, all resident (<=148 SMs)
#define BPB  (NBLK / BB)  // 32 blocks per batch

// -------- scratch (device globals; no allocation allowed) --------
__device__ float d_C[NROWS * I1];        // per-row y-part, scale folded (cross-block)
__device__ unsigned int d_bar4[BB];      // per-batch monotonic barrier counters

// ---------------- single fused kernel ----------------
// 128 blocks x 8 warps, 8 rows/block.
//   pre-barrier : stage val -> layer-1 GEMM -> store C -> fence -> ARRIVE (batch ctr)
//   overlap     : fold W2/W3, mask compaction, A finalize, con copy
//   wait        : nanosleep spin until the 32 blocks of THIS batch arrived
//   post        : warp-per-row sparse MLP, direct var writes
__global__ void __launch_bounds__(256) fused_kernel(const float* __restrict__ mat,
                                                    const float* __restrict__ val,
                                                    const float* __restrict__ M1,
                                                    const float* __restrict__ B1,
                                                    const float* __restrict__ M2,
                                                    const float* __restrict__ B2,
                                                    const float* __restrict__ M3,
                                                    const float* __restrict__ B3,
                                                    const float* __restrict__ g1,
                                                    const float* __restrict__ b1,
                                                    const float* __restrict__ m1,
                                                    const float* __restrict__ v1,
                                                    const float* __restrict__ g2,
                                                    const float* __restrict__ b2,
                                                    const float* __restrict__ m2,
                                                    const float* __restrict__ v2,
                                                    const float* __restrict__ g3,
                                                    const float* __restrict__ b3,
                                                    const float* __restrict__ m3,
                                                    const float* __restrict__ v3,
                                                    float* __restrict__ out) {
    __shared__ float W2t[I2 * 68];         // 8.5 KB folded W2, transposed [col][j]
    __shared__ float4 W3p[I2 * 32];        // 16 KB folded W3, [j][lane]=cols 3l..3l+2
    __shared__ float b2s[I2];
    __shared__ float b3s[PK];
    __shared__ float axs[8][I1];           // 2 KB  A rows (block-local)
    __shared__ int ylist[8][MAXY];         // 2 KB
    __shared__ float yvs[8][MAXY];         // 2 KB
    __shared__ float s1s[8][4][I1];        // 8 KB
    __shared__ float s2s[8][4][I2];        // 4 KB
    __shared__ float vs[8][PARAM];         // 4 KB
    __shared__ float buf[2][8][I1];        // 4 KB

    int t = threadIdx.x;
    int lane = t & 31;
    int w = t >> 5;              // 0..7 = row within block
    int row0 = blockIdx.x * 8;
    int row = row0 + w;
    int b = row >> 8;            // == blockIdx.x >> 5
    int bat = blockIdx.x >> 5;   // batch 0..3 (32 blocks each)

    // ===== pre-barrier: stage val rows =====
    for (int i = t; i < 8 * PARAM; i += 256)
        vs[i >> 7][i & 127] = val[row0 * PARAM + i];
    __syncthreads();

    // ===== pre-barrier: layer-1 GEMM (both halves of M1) =====
    {
        int j = t & 63;
        int part = (t >> 6) & 1;          // 0 = M1[:128], 1 = M1[128:]
        int half = t >> 7;                // rows half*4 .. half*4+3
        float sumA[4] = {0.f, 0.f, 0.f, 0.f};
        float sumB[4] = {0.f, 0.f, 0.f, 0.f};
        const float* Mp = M1 + part * PARAM * I1 + j;
#pragma unroll
        for (int k = 0; k < PARAM; k += 8) {
            float a0 = Mp[(k + 0) * I1], a1 = Mp[(k + 1) * I1];
            float a2 = Mp[(k + 2) * I1], a3 = Mp[(k + 3) * I1];
            float c0 = Mp[(k + 4) * I1], c1 = Mp[(k + 5) * I1];
            float c2 = Mp[(k + 6) * I1], c3 = Mp[(k + 7) * I1];
#pragma unroll
            for (int r = 0; r < 4; r++) {
                float4 va = *(const float4*)&vs[half * 4 + r][k];
                float4 vb = *(const float4*)&vs[half * 4 + r][k + 4];
                sumA[r] = fmaf(va.x, a0, fmaf(va.y, a1, fmaf(va.z, a2, fmaf(va.w, a3, sumA[r]))));
                sumB[r] = fmaf(vb.x, c0, fmaf(vb.y, c1, fmaf(vb.z, c2, fmaf(vb.w, c3, sumB[r]))));
            }
        }
#pragma unroll
        for (int r = 0; r < 4; r++) buf[part][half * 4 + r][j] = sumA[r] + sumB[r];
        __syncthreads();
        // C to global NOW (the only cross-block data)
        if (part == 1) {
            float sc = g1[j] * rsqrtf(v1[j] + EPS);
#pragma unroll
            for (int r = 0; r < 4; r++) {
                int rr = half * 4 + r;
                d_C[(row0 + rr) * I1 + j] = buf[1][rr][j] * sc;
            }
        }
    }

    // ===== arrive on batch counter (release C writes) =====
    __threadfence();
    __syncthreads();
    if (t == 0) atomicAdd(&d_bar4[bat], 1u);

    // ===== overlap window: block-local prep while batch peers finish =====
    // fold BN2 into W2 (transposed, padded)
    for (int i = t; i < I1 * I2; i += 256) {
        int col = i & 31, j = i >> 5;
        float s = g2[col] * rsqrtf(v2[col] + EPS);
        W2t[col * 68 + j] = M2[j * I2 + col] * s;
    }
    // fold BN3 into W3, packed float4 [j][l] = cols 3l,3l+1,3l+2,0
    {
        float* W3f = (float*)W3p;
        for (int i = t; i < I2 * 128; i += 256) {
            int j = i >> 7, q = i & 127, l = q >> 2, d = q & 3;
            float vvv = 0.f;
            if (d < 3) {
                int col = 3 * l + d;
                vvv = M3[j * PK + col] * (g3[col] * rsqrtf(v3[col] + EPS));
            }
            W3f[i] = vvv;
        }
    }
    if (t < I2) {
        float s = g2[t] * rsqrtf(v2[t] + EPS);
        b2s[t] = B2[t] * s + (b2[t] - m2[t] * s);
    }
    if (t >= 128 && t < 128 + PK) {
        int k = t - 128;
        float s = g3[k] * rsqrtf(v3[k] + EPS);
        b3s[k] = B3[k] * s + (b3[k] - m3[k] * s);
    }
    // A finalize (block-local, from buf)
    {
        int j = t & 63;
        int part = (t >> 6) & 1;
        int half = t >> 7;
        if (part == 0) {
            float sc = g1[j] * rsqrtf(v1[j] + EPS);
            float bb = B1[j] * sc + (b1[j] - m1[j] * sc);
#pragma unroll
            for (int r = 0; r < 4; r++) {
                int rr = half * 4 + r;
                axs[rr][j] = (buf[0][rr][j] - buf[1][rr][j]) * sc + bb;
            }
        }
    }
    // per-warp mask compaction (deterministic ballot prefix); n4 stays in regs
    int n4;
    {
        int cnt = 0;
#pragma unroll
        for (int c = 0; c < GS / 32; c++) {
            int idx = c * 32 + lane;
            float mv = mat[row * GS + idx];
            unsigned msk = __ballot_sync(0xffffffffu, mv != 0.0f);
            if (mv != 0.0f) {
                int off = cnt + __popc(msk & ((1u << lane) - 1u));
                ylist[w][off] = idx;
                yvs[w][off] = mv;
            }
            cnt += __popc(msk);
        }
        n4 = (cnt + 3) & ~3;
        for (int k = cnt + lane; k < n4; k += 32) { ylist[w][k] = 0; yvs[w][k] = 0.f; }
    }
    // con copy (independent of everything)
    out[row * PARAM + lane] = vs[w][lane];
    __syncwarp();

    // ===== wait for the 32 blocks of this batch (nanosleep spin) =====
    __syncthreads();             // block-local prep done
    if (t == 0) {
        unsigned seen = atomicAdd(&d_bar4[bat], 0u);
        unsigned target = ((seen - 1u) / (unsigned)BPB + 1u) * (unsigned)BPB;
        while (*(volatile unsigned*)&d_bar4[bat] < target) { __nanosleep(64); }
    }
    __syncthreads();

    // ===== phase 2: warp-per-row sparse MLP =====
    float axl = axs[w][lane];
    float axh = axs[w][lane + 32];
    float b2l = b2s[lane];
    float b30 = b3s[3 * lane], b31 = b3s[3 * lane + 1], b32 = b3s[3 * lane + 2];
    float a0 = 0.f, a1 = 0.f, a2 = 0.f;

    const float* Cb = d_C + b * GS * I1;

    float cl[4], ch[4];
    if (n4 > 0) {
#pragma unroll
        for (int p = 0; p < 4; p++) {
            const float* cy = Cb + ylist[w][p] * I1;
            cl[p] = __ldg(cy + lane);
            ch[p] = __ldg(cy + lane + 32);
        }
    }

    for (int i0 = 0; i0 < n4; i0 += 4) {
#pragma unroll
        for (int p = 0; p < 4; p++) {
            s1s[w][p][lane] = fmaxf(axl + cl[p], 0.f);
            s1s[w][p][lane + 32] = fmaxf(axh + ch[p], 0.f);
        }
        __syncwarp();
        if (i0 + 4 < n4) {
#pragma unroll
            for (int p = 0; p < 4; p++) {
                const float* cy = Cb + ylist[w][i0 + 4 + p] * I1;
                cl[p] = __ldg(cy + lane);
                ch[p] = __ldg(cy + lane + 32);
            }
        }
        float s2p0 = b2l, s2p1 = b2l, s2p2 = b2l, s2p3 = b2l;
        float r0 = 0.f, r1 = 0.f, r2 = 0.f, r3 = 0.f;
        const float4* w2v = (const float4*)&W2t[lane * 68];
        const float4* v0p = (const float4*)s1s[w][0];
        const float4* v1p = (const float4*)s1s[w][1];
        const float4* v2p = (const float4*)s1s[w][2];
        const float4* v3p = (const float4*)s1s[w][3];
#pragma unroll
        for (int q = 0; q < 16; q += 2) {
            float4 wa = w2v[q], wb = w2v[q + 1];
            float4 v0 = v0p[q], v1 = v1p[q], v2 = v2p[q], v3 = v3p[q];
            float4 u0 = v0p[q + 1], u1 = v1p[q + 1], u2 = v2p[q + 1], u3 = v3p[q + 1];
            s2p0 = fmaf(v0.x, wa.x, s2p0); s2p0 = fmaf(v0.y, wa.y, s2p0);
            s2p0 = fmaf(v0.z, wa.z, s2p0); s2p0 = fmaf(v0.w, wa.w, s2p0);
            r0 = fmaf(u0.x, wb.x, r0); r0 = fmaf(u0.y, wb.y, r0);
            r0 = fmaf(u0.z, wb.z, r0); r0 = fmaf(u0.w, wb.w, r0);
            s2p1 = fmaf(v1.x, wa.x, s2p1); s2p1 = fmaf(v1.y, wa.y, s2p1);
            s2p1 = fmaf(v1.z, wa.z, s2p1); s2p1 = fmaf(v1.w, wa.w, s2p1);
            r1 = fmaf(u1.x, wb.x, r1); r1 = fmaf(u1.y, wb.y, r1);
            r1 = fmaf(u1.z, wb.z, r1); r1 = fmaf(u1.w, wb.w, r1);
            s2p2 = fmaf(v2.x, wa.x, s2p2); s2p2 = fmaf(v2.y, wa.y, s2p2);
            s2p2 = fmaf(v2.z, wa.z, s2p2); s2p2 = fmaf(v2.w, wa.w, s2p2);
            r2 = fmaf(u2.x, wb.x, r2); r2 = fmaf(u2.y, wb.y, r2);
            r2 = fmaf(u2.z, wb.z, r2); r2 = fmaf(u2.w, wb.w, r2);
            s2p3 = fmaf(v3.x, wa.x, s2p3); s2p3 = fmaf(v3.y, wa.y, s2p3);
            s2p3 = fmaf(v3.z, wa.z, s2p3); s2p3 = fmaf(v3.w, wa.w, s2p3);
            r3 = fmaf(u3.x, wb.x, r3); r3 = fmaf(u3.y, wb.y, r3);
            r3 = fmaf(u3.z, wb.z, r3); r3 = fmaf(u3.w, wb.w, r3);
        }
        s2s[w][0][lane] = fmaxf(s2p0 + r0, 0.f);
        s2s[w][1][lane] = fmaxf(s2p1 + r1, 0.f);
        s2s[w][2][lane] = fmaxf(s2p2 + r2, 0.f);
        s2s[w][3][lane] = fmaxf(s2p3 + r3, 0.f);
        __syncwarp();
        float t00 = b30, t01 = b31, t02 = b32;
        float t10 = b30, t11 = b31, t12 = b32;
        float t20 = b30, t21 = b31, t22 = b32;
        float t30 = b30, t31 = b31, t32 = b32;
        const float4* u0p = (const float4*)s2s[w][0];
        const float4* u1p = (const float4*)s2s[w][1];
        const float4* u2p = (const float4*)s2s[w][2];
        const float4* u3p = (const float4*)s2s[w][3];
#pragma unroll
        for (int jq = 0; jq < 8; jq++) {
            float4 u0 = u0p[jq], u1 = u1p[jq], u2 = u2p[jq], u3 = u3p[jq];
            float s0v[4] = {u0.x, u0.y, u0.z, u0.w};
            float s1v[4] = {u1.x, u1.y, u1.z, u1.w};
            float s2v[4] = {u2.x, u2.y, u2.z, u2.w};
            float s3v[4] = {u3.x, u3.y, u3.z, u3.w};
#pragma unroll
            for (int d = 0; d < 4; d++) {
                float4 wv = W3p[(4 * jq + d) * 32 + lane];
                t00 = fmaf(s0v[d], wv.x, t00); t01 = fmaf(s0v[d], wv.y, t01); t02 = fmaf(s0v[d], wv.z, t02);
                t10 = fmaf(s1v[d], wv.x, t10); t11 = fmaf(s1v[d], wv.y, t11); t12 = fmaf(s1v[d], wv.z, t12);
                t20 = fmaf(s2v[d], wv.x, t20); t21 = fmaf(s2v[d], wv.y, t21); t22 = fmaf(s2v[d], wv.z, t22);
                t30 = fmaf(s3v[d], wv.x, t30); t31 = fmaf(s3v[d], wv.y, t31); t32 = fmaf(s3v[d], wv.z, t32);
            }
        }
        float m0 = yvs[w][i0], m1v = yvs[w][i0 + 1], m2v = yvs[w][i0 + 2], m3v = yvs[w][i0 + 3];
        a0 = fmaf(fmaxf(t00, 0.f), m0, a0); a1 = fmaf(fmaxf(t01, 0.f), m0, a1); a2 = fmaf(fmaxf(t02, 0.f), m0, a2);
        a0 = fmaf(fmaxf(t10, 0.f), m1v, a0); a1 = fmaf(fmaxf(t11, 0.f), m1v, a1); a2 = fmaf(fmaxf(t12, 0.f), m1v, a2);
        a0 = fmaf(fmaxf(t20, 0.f), m2v, a0); a1 = fmaf(fmaxf(t21, 0.f), m2v, a1); a2 = fmaf(fmaxf(t22, 0.f), m2v, a2);
        a0 = fmaf(fmaxf(t30, 0.f), m3v, a0); a1 = fmaf(fmaxf(t31, 0.f), m3v, a1); a2 = fmaf(fmaxf(t32, 0.f), m3v, a2);
    }

    // ===== epilogue: var writes only (con already copied in overlap window) =====
    float* orow = out + row * PARAM;
    orow[KC + 3 * lane + 0] = fminf(fmaxf(a0 * (1.f / 16.f), -1.f), 1.f);
    orow[KC + 3 * lane + 1] = fminf(fmaxf(a1 * (1.f / 16.f), -1.f), 1.f);
    orow[KC + 3 * lane + 2] = fminf(fmaxf(a2 * (1.f / 16.f), -1.f), 1.f);
}

extern "C" void kernel_launch(void* const* d_in, const int* in_sizes, int n_in,
                              void* d_out, int out_size) {
    const float* mat = (const float*)d_in[0];
    const float* val = (const float*)d_in[1];
    const float* M1  = (const float*)d_in[2];
    const float* B1  = (const float*)d_in[3];
    const float* M2  = (const float*)d_in[4];
    const float* B2  = (const float*)d_in[5];
    const float* M3  = (const float*)d_in[6];
    const float* B3  = (const float*)d_in[7];
    const float* g1  = (const float*)d_in[8];
    const float* b1  = (const float*)d_in[9];
    const float* m1  = (const float*)d_in[10];
    const float* v1  = (const float*)d_in[11];
    const float* g2  = (const float*)d_in[12];
    const float* b2  = (const float*)d_in[13];
    const float* m2  = (const float*)d_in[14];
    const float* v2  = (const float*)d_in[15];
    const float* g3  = (const float*)d_in[16];
    const float* b3  = (const float*)d_in[17];
    const float* m3  = (const float*)d_in[18];
    const float* v3  = (const float*)d_in[19];
    float* out = (float*)d_out;

    fused_kernel<<<NBLK, 256>>>(mat, val, M1, B1, M2, B2, M3, B3,
                                g1, b1, m1, v1, g2, b2, m2, v2,
                                g3, b3, m3, v3, out);
}